// round 7
// baseline (speedup 1.0000x reference)
#include <cuda_runtime.h>
#include <math.h>

#define V 50257
#define H 1024
#define S 2048
#define NATTN 128               // attention blocks (wave-1 resident by ID)
#define NBK 3142                // ceil(V/16), 16 rows per logits block
#define GRID_A (NATTN + NBK)

// out layout: [0,V) log_softmax | [V,V+H) context | [V+H,V+3H) hidden | [V+3H,V+3H+S) attn
#define OUT_CTX  (V)
#define OUT_HID  (V + H)
#define OUT_ATTN (V + 3*H)

// float4-accessed globals MUST be 16B aligned (round-4 trap)
__device__ __align__(16) float g_h0[H];
__device__ __align__(16) float g_h1[H];
__device__ __align__(16) float g_v[H];
__device__ __align__(16) float g_context[H];
__device__ __align__(16) float g_logits[V];
__device__ __align__(16) float g_part[NBK * 16];  // h1-half partial per row
__device__ float g_apm[NATTN];
__device__ float g_aps[NATTN];
__device__ float g_pm[NBK];
__device__ float g_ps[NBK];
__device__ unsigned g_barrier;     // attention-internal barrier

__device__ __forceinline__ float warp_sum(float v) {
    #pragma unroll
    for (int o = 16; o; o >>= 1) v += __shfl_down_sync(0xffffffffu, v, o);
    return v;
}
__device__ __forceinline__ float warp_max(float v) {
    #pragma unroll
    for (int o = 16; o; o >>= 1) v = fmaxf(v, __shfl_down_sync(0xffffffffu, v, o));
    return v;
}
__device__ __forceinline__ float dot4(float4 a, float4 b) {
    return a.x*b.x + a.y*b.y + a.z*b.z + a.w*b.w;
}
// barrier among the NATTN attention blocks only (IDs 0..127 -> wave-1 resident)
__device__ __forceinline__ void attn_barrier(unsigned target) {
    __syncthreads();
    if (threadIdx.x == 0) {
        __threadfence();
        atomicAdd(&g_barrier, 1u);
        volatile unsigned* p = &g_barrier;
        while (*p < target) __nanosleep(32);
        __threadfence();
    }
    __syncthreads();
}

// ---------------- GRU cell. Block k computes h_new[k]. 256 threads.
template<bool SPLIT>
__global__ void k_gru(const int* __restrict__ word,
                      const float* __restrict__ emb,
                      const float* __restrict__ xb,
                      const float* __restrict__ xdirect,
                      const float* __restrict__ hprev,
                      const float* __restrict__ Wih,
                      const float* __restrict__ Whh,
                      const float* __restrict__ bih,
                      const float* __restrict__ bhh,
                      float* __restrict__ hnew,
                      float* __restrict__ out_hidden,
                      int zero_pass) {
    const int k = blockIdx.x;
    const int t = threadIdx.x;
    if (zero_pass && t == 0) {
        g_v[k] = 0.f;
        g_context[k] = 0.f;
        if (k == 0) g_barrier = 0u;
    }

    float acc[6];
    const float4* xa4 = nullptr;
    const float4* xb4 = nullptr;
    const float4* xd4 = nullptr;
    if (SPLIT) {
        int wi = word[0];
        xa4 = (const float4*)(emb + (size_t)wi * H);
        xb4 = (const float4*)xb;
    } else {
        xd4 = (const float4*)xdirect;
    }
    const float4* h4 = (const float4*)hprev;
    const int XDIM = SPLIT ? 2*H : H;

    #pragma unroll
    for (int g = 0; g < 3; g++) {
        const float* wrow = Wih + (size_t)(g * H + k) * XDIM;
        float a;
        if (SPLIT) {
            a  = dot4(((const float4*)wrow)[t],       xa4[t]);
            a += dot4(((const float4*)(wrow + H))[t], xb4[t]);
        } else {
            a  = dot4(((const float4*)wrow)[t],       xd4[t]);
        }
        acc[g] = a;
    }
    #pragma unroll
    for (int g = 0; g < 3; g++) {
        const float* wrow = Whh + (size_t)(g * H + k) * H;
        acc[3 + g] = dot4(((const float4*)wrow)[t], h4[t]);
    }

    __shared__ float red[6][8];
    int w = t >> 5, lane = t & 31;
    #pragma unroll
    for (int g = 0; g < 6; g++) {
        float s = warp_sum(acc[g]);
        if (lane == 0) red[g][w] = s;
    }
    __syncthreads();
    if (t == 0) {
        float s[6];
        #pragma unroll
        for (int g = 0; g < 6; g++) {
            float a = 0.f;
            #pragma unroll
            for (int j = 0; j < 8; j++) a += red[g][j];
            s[g] = a;
        }
        float ir = s[0] + bih[k],       hr = s[3] + bhh[k];
        float iz = s[1] + bih[H + k],   hz = s[4] + bhh[H + k];
        float in_= s[2] + bih[2*H + k], hn = s[5] + bhh[2*H + k];
        float r = 1.f / (1.f + expf(-(ir + hr)));
        float z = 1.f / (1.f + expf(-(iz + hz)));
        float n = tanhf(in_ + r * hn);
        float hv = (1.f - z) * n + z * hprev[k];
        hnew[k] = hv;
        out_hidden[k] = hv;
    }
}

// ---------------- Kernel A: blocks [0,NATTN) fused attention (independent);
// blocks [NATTN,GRID_A): h1-half of W_out, 2 rows/warp (16 loads/lane) -> g_part.
__global__ void __launch_bounds__(256) kA(const float* __restrict__ Wa,
                                          const float* __restrict__ enc,
                                          const float* __restrict__ Wout,
                                          float* __restrict__ out_attn) {
    const int t = threadIdx.x;
    const int w = t >> 5, lane = t & 31;

    if (blockIdx.x < NATTN) {
        // ===== attention =====
        const int b = blockIdx.x;
        __shared__ float h1s[8];
        __shared__ float sc[16];
        __shared__ float attnw[16];
        __shared__ float red[8];
        __shared__ float sM, sInvS;

        if (t < 8) h1s[t] = g_h1[b * 8 + t];
        __syncthreads();
        {
            const float4* Wa4 = (const float4*)(Wa + (size_t)(b * 8) * H);
            float4 a = make_float4(0.f, 0.f, 0.f, 0.f);
            #pragma unroll
            for (int j = 0; j < 8; j++) {
                float4 wv = Wa4[j * 256 + t];
                float hv = h1s[j];
                a.x += wv.x * hv; a.y += wv.y * hv; a.z += wv.z * hv; a.w += wv.w * hv;
            }
            atomicAdd(&g_v[4*t + 0], a.x);
            atomicAdd(&g_v[4*t + 1], a.y);
            atomicAdd(&g_v[4*t + 2], a.z);
            atomicAdd(&g_v[4*t + 3], a.w);
        }
        attn_barrier(NATTN);

        const int s0 = b * 16;
        {
            const float4* v4 = (const float4*)g_v;
            float4 vv[8];
            #pragma unroll
            for (int i = 0; i < 8; i++) vv[i] = v4[lane + 32*i];
            const float4* e4a = (const float4*)(enc + (size_t)(s0 + 2*w)     * H);
            const float4* e4b = (const float4*)(enc + (size_t)(s0 + 2*w + 1) * H);
            float acc0 = 0.f, acc1 = 0.f;
            #pragma unroll
            for (int i = 0; i < 8; i++) {
                acc0 += dot4(e4a[lane + 32*i], vv[i]);
                acc1 += dot4(e4b[lane + 32*i], vv[i]);
            }
            acc0 = warp_sum(acc0);
            acc1 = warp_sum(acc1);
            if (lane == 0) { sc[2*w] = acc0; sc[2*w + 1] = acc1; }
        }
        __syncthreads();
        if (t == 0) {
            float m = -INFINITY;
            #pragma unroll
            for (int j = 0; j < 16; j++) m = fmaxf(m, sc[j]);
            float s = 0.f;
            #pragma unroll
            for (int j = 0; j < 16; j++) s += expf(sc[j] - m);
            g_apm[b] = m;
            g_aps[b] = s;
        }
        attn_barrier(2 * NATTN);

        {
            float m = (t < NATTN) ? g_apm[t] : -INFINITY;
            m = warp_max(m);
            if (lane == 0) red[w] = m;
            __syncthreads();
            if (t == 0) {
                float M = -INFINITY;
                #pragma unroll
                for (int j = 0; j < 8; j++) M = fmaxf(M, red[j]);
                sM = M;
            }
            __syncthreads();
            float e = (t < NATTN) ? g_aps[t] * expf(g_apm[t] - sM) : 0.f;
            e = warp_sum(e);
            if (lane == 0) red[w] = e;
            __syncthreads();
            if (t == 0) {
                float Ssum = 0.f;
                #pragma unroll
                for (int j = 0; j < 8; j++) Ssum += red[j];
                sInvS = 1.f / Ssum;
            }
            __syncthreads();
            if (t < 16) {
                float a = expf(sc[t] - sM) * sInvS;
                attnw[t] = a;
                out_attn[s0 + t] = a;
            }
            __syncthreads();
        }
        {
            const float4* e4 = (const float4*)(enc + (size_t)s0 * H);
            float4 c = make_float4(0.f, 0.f, 0.f, 0.f);
            #pragma unroll
            for (int r = 0; r < 16; r++) {
                float av = attnw[r];
                float4 e = e4[r * 256 + t];
                c.x += av * e.x; c.y += av * e.y; c.z += av * e.z; c.w += av * e.w;
            }
            atomicAdd(&g_context[4*t + 0], c.x);
            atomicAdd(&g_context[4*t + 1], c.y);
            atomicAdd(&g_context[4*t + 2], c.z);
            atomicAdd(&g_context[4*t + 3], c.w);
        }
    } else {
        // ===== h1-half logits partial: 2 rows per warp, 16 loads/lane =====
        const int bb = blockIdx.x - NATTN;
        __shared__ __align__(16) float qs[H];
        for (int i = t; i < H; i += 256) qs[i] = g_h1[i];
        __syncthreads();
        const int r0 = bb * 16 + 2 * w;
        const int r1 = r0 + 1;
        const float4* q4 = (const float4*)qs;
        if (r1 < V) {
            const float4* wr0 = (const float4*)(Wout + (size_t)r0 * (2*H));
            const float4* wr1 = (const float4*)(Wout + (size_t)r1 * (2*H));
            float a0 = 0.f, a1 = 0.f;
            #pragma unroll
            for (int i = 0; i < 8; i++) {
                float4 qv = q4[lane + i*32];
                a0 += dot4(wr0[lane + i*32], qv);
                a1 += dot4(wr1[lane + i*32], qv);
            }
            a0 = warp_sum(a0);
            a1 = warp_sum(a1);
            if (lane == 0) { g_part[r0] = a0; g_part[r1] = a1; }
        } else if (r0 < V) {
            const float4* wr0 = (const float4*)(Wout + (size_t)r0 * (2*H));
            float a0 = 0.f;
            #pragma unroll
            for (int i = 0; i < 8; i++)
                a0 += dot4(wr0[lane + i*32], q4[lane + i*32]);
            a0 = warp_sum(a0);
            if (lane == 0) g_part[r0] = a0;
        }
    }
}

// ---------------- Kernel B: ctx-half, 2 rows/warp + combine -> logits + partials
__global__ void __launch_bounds__(256) kB(const float* __restrict__ Wout,
                                          const float* __restrict__ bout) {
    const int t = threadIdx.x;
    const int w = t >> 5, lane = t & 31;
    __shared__ __align__(16) float qs[H];
    __shared__ float blog[16];
    for (int i = t; i < H; i += 256) qs[i] = g_context[i];
    __syncthreads();

    const int r0 = blockIdx.x * 16 + 2 * w;
    const int r1 = r0 + 1;
    const float4* q4 = (const float4*)qs;
    float l0 = -INFINITY, l1 = -INFINITY;
    if (r1 < V) {
        const float4* wr0 = (const float4*)(Wout + (size_t)r0 * (2*H) + H);
        const float4* wr1 = (const float4*)(Wout + (size_t)r1 * (2*H) + H);
        float a0 = 0.f, a1 = 0.f;
        #pragma unroll
        for (int i = 0; i < 8; i++) {
            float4 qv = q4[lane + i*32];
            a0 += dot4(wr0[lane + i*32], qv);
            a1 += dot4(wr1[lane + i*32], qv);
        }
        a0 = warp_sum(a0);
        a1 = warp_sum(a1);
        if (lane == 0) {
            l0 = a0 + g_part[r0] + bout[r0];
            l1 = a1 + g_part[r1] + bout[r1];
            g_logits[r0] = l0;
            g_logits[r1] = l1;
        }
    } else if (r0 < V) {
        const float4* wr0 = (const float4*)(Wout + (size_t)r0 * (2*H) + H);
        float a0 = 0.f;
        #pragma unroll
        for (int i = 0; i < 8; i++)
            a0 += dot4(wr0[lane + i*32], q4[lane + i*32]);
        a0 = warp_sum(a0);
        if (lane == 0) {
            l0 = a0 + g_part[r0] + bout[r0];
            g_logits[r0] = l0;
        }
    }
    if (lane == 0) { blog[2*w] = l0; blog[2*w + 1] = l1; }
    __syncthreads();
    if (t == 0) {
        float m = -INFINITY;
        #pragma unroll
        for (int j = 0; j < 16; j++) m = fmaxf(m, blog[j]);
        float s = 0.f;
        #pragma unroll
        for (int j = 0; j < 16; j++)
            if (blog[j] > -INFINITY) s += expf(blog[j] - m);
        g_pm[blockIdx.x] = m;
        g_ps[blockIdx.x] = s;
    }
}

// ---------------- K9: each block redundantly reduces partials (L2-hot), then
// normalizes its 256-element slice. Block 0 also emits context.
__global__ void __launch_bounds__(256) k9_final(float* __restrict__ out,
                                                float* __restrict__ out_ctx) {
    const int t = threadIdx.x;
    const int w = t >> 5, lane = t & 31;
    __shared__ float red[8];
    __shared__ float sM, sL;

    if (blockIdx.x == 0) {
        for (int i = t; i < H; i += 256) out_ctx[i] = g_context[i];
    }

    float m = -INFINITY;
    for (int i = t; i < NBK; i += 256) m = fmaxf(m, __ldg(&g_pm[i]));
    m = warp_max(m);
    if (lane == 0) red[w] = m;
    __syncthreads();
    if (t == 0) {
        float M = -INFINITY;
        #pragma unroll
        for (int j = 0; j < 8; j++) M = fmaxf(M, red[j]);
        sM = M;
    }
    __syncthreads();
    float M = sM;
    float s = 0.f;
    for (int i = t; i < NBK; i += 256) s += __ldg(&g_ps[i]) * expf(__ldg(&g_pm[i]) - M);
    s = warp_sum(s);
    if (lane == 0) red[w] = s;
    __syncthreads();
    if (t == 0) {
        float Ssum = 0.f;
        #pragma unroll
        for (int j = 0; j < 8; j++) Ssum += red[j];
        sL = M + logf(Ssum);
    }
    __syncthreads();
    float shift = sL;
    int v = blockIdx.x * 256 + t;
    if (v < V) out[v] = g_logits[v] - shift;
}

extern "C" void kernel_launch(void* const* d_in, const int* in_sizes, int n_in,
                              void* d_out, int out_size) {
    const int*   word     = (const int*)  d_in[0];
    const float* last_ctx = (const float*)d_in[1];
    const float* last_hid = (const float*)d_in[2];
    const float* enc      = (const float*)d_in[3];
    const float* emb      = (const float*)d_in[4];
    const float* W_ih0    = (const float*)d_in[5];
    const float* W_hh0    = (const float*)d_in[6];
    const float* b_ih0    = (const float*)d_in[7];
    const float* b_hh0    = (const float*)d_in[8];
    const float* W_ih1    = (const float*)d_in[9];
    const float* W_hh1    = (const float*)d_in[10];
    const float* b_ih1    = (const float*)d_in[11];
    const float* b_hh1    = (const float*)d_in[12];
    const float* Wa       = (const float*)d_in[13];
    // d_in[14] = ba (cancels under softmax shift-invariance)
    const float* W_out    = (const float*)d_in[15];
    const float* b_out    = (const float*)d_in[16];
    float* out = (float*)d_out;

    float *g_h0_p, *g_h1_p;
    cudaGetSymbolAddress((void**)&g_h0_p, g_h0);
    cudaGetSymbolAddress((void**)&g_h1_p, g_h1);

    k_gru<true ><<<H, 256>>>(word, emb, last_ctx, nullptr, last_hid,
                             W_ih0, W_hh0, b_ih0, b_hh0,
                             g_h0_p, out + OUT_HID, 0);
    k_gru<false><<<H, 256>>>(nullptr, nullptr, nullptr, g_h0_p, last_hid + H,
                             W_ih1, W_hh1, b_ih1, b_hh1,
                             g_h1_p, out + OUT_HID + H, 1);
    kA<<<GRID_A, 256>>>(Wa, enc, W_out, out + OUT_ATTN);
    kB<<<NBK, 256>>>(W_out, b_out);
    k9_final<<<(V + 255) / 256, 256>>>(out, out + OUT_CTX);
}

// round 8
// speedup vs baseline: 1.1653x; 1.1653x over previous
#include <cuda_runtime.h>
#include <math.h>

#define V 50257
#define H 1024
#define S 2048
#define NATTN 128               // attention blocks (wave-1 resident by ID)
#define NBK 6283                // ceil(V/8), 8 rows per logits block
#define GRID_A (NATTN + NBK)

// out layout: [0,V) log_softmax | [V,V+H) context | [V+H,V+3H) hidden | [V+3H,V+3H+S) attn
#define OUT_CTX  (V)
#define OUT_HID  (V + H)
#define OUT_ATTN (V + 3*H)

// float4-accessed globals MUST be 16B aligned (round-4 trap)
__device__ __align__(16) float g_h0[H];
__device__ __align__(16) float g_h1[H];
__device__ __align__(16) float g_v[H];
__device__ __align__(16) float g_context[H];
__device__ __align__(16) float g_logits[V];
__device__ __align__(16) float g_part[NBK * 8];   // h1-half partial per row
__device__ float g_apm[NATTN];
__device__ float g_aps[NATTN];
__device__ float g_sumexpv;        // global sum of exp(logit), shift 0 (logits are O(1))
__device__ unsigned g_barrier;     // attention-internal barrier

__device__ __forceinline__ float warp_sum(float v) {
    #pragma unroll
    for (int o = 16; o; o >>= 1) v += __shfl_down_sync(0xffffffffu, v, o);
    return v;
}
__device__ __forceinline__ float warp_max(float v) {
    #pragma unroll
    for (int o = 16; o; o >>= 1) v = fmaxf(v, __shfl_down_sync(0xffffffffu, v, o));
    return v;
}
__device__ __forceinline__ float dot4(float4 a, float4 b) {
    return a.x*b.x + a.y*b.y + a.z*b.z + a.w*b.w;
}
// barrier among the NATTN attention blocks only (IDs 0..127 -> wave-1 resident)
__device__ __forceinline__ void attn_barrier(unsigned target) {
    __syncthreads();
    if (threadIdx.x == 0) {
        __threadfence();
        atomicAdd(&g_barrier, 1u);
        volatile unsigned* p = &g_barrier;
        while (*p < target) __nanosleep(32);
        __threadfence();
    }
    __syncthreads();
}

// ---------------- GRU cell. Block k computes h_new[k]. 256 threads.
template<bool SPLIT>
__global__ void k_gru(const int* __restrict__ word,
                      const float* __restrict__ emb,
                      const float* __restrict__ xb,
                      const float* __restrict__ xdirect,
                      const float* __restrict__ hprev,
                      const float* __restrict__ Wih,
                      const float* __restrict__ Whh,
                      const float* __restrict__ bih,
                      const float* __restrict__ bhh,
                      float* __restrict__ hnew,
                      float* __restrict__ out_hidden,
                      int zero_pass) {
    const int k = blockIdx.x;
    const int t = threadIdx.x;
    if (zero_pass && t == 0) {
        g_v[k] = 0.f;
        g_context[k] = 0.f;
        if (k == 0) { g_barrier = 0u; g_sumexpv = 0.f; }
    }

    float acc[6];
    const float4* xa4 = nullptr;
    const float4* xb4 = nullptr;
    const float4* xd4 = nullptr;
    if (SPLIT) {
        int wi = word[0];
        xa4 = (const float4*)(emb + (size_t)wi * H);
        xb4 = (const float4*)xb;
    } else {
        xd4 = (const float4*)xdirect;
    }
    const float4* h4 = (const float4*)hprev;
    const int XDIM = SPLIT ? 2*H : H;

    #pragma unroll
    for (int g = 0; g < 3; g++) {
        const float* wrow = Wih + (size_t)(g * H + k) * XDIM;
        float a;
        if (SPLIT) {
            a  = dot4(((const float4*)wrow)[t],       xa4[t]);
            a += dot4(((const float4*)(wrow + H))[t], xb4[t]);
        } else {
            a  = dot4(((const float4*)wrow)[t],       xd4[t]);
        }
        acc[g] = a;
    }
    #pragma unroll
    for (int g = 0; g < 3; g++) {
        const float* wrow = Whh + (size_t)(g * H + k) * H;
        acc[3 + g] = dot4(((const float4*)wrow)[t], h4[t]);
    }

    __shared__ float red[6][8];
    int w = t >> 5, lane = t & 31;
    #pragma unroll
    for (int g = 0; g < 6; g++) {
        float s = warp_sum(acc[g]);
        if (lane == 0) red[g][w] = s;
    }
    __syncthreads();
    if (t == 0) {
        float s[6];
        #pragma unroll
        for (int g = 0; g < 6; g++) {
            float a = 0.f;
            #pragma unroll
            for (int j = 0; j < 8; j++) a += red[g][j];
            s[g] = a;
        }
        float ir = s[0] + bih[k],       hr = s[3] + bhh[k];
        float iz = s[1] + bih[H + k],   hz = s[4] + bhh[H + k];
        float in_= s[2] + bih[2*H + k], hn = s[5] + bhh[2*H + k];
        float r = 1.f / (1.f + expf(-(ir + hr)));
        float z = 1.f / (1.f + expf(-(iz + hz)));
        float n = tanhf(in_ + r * hn);
        float hv = (1.f - z) * n + z * hprev[k];
        hnew[k] = hv;
        out_hidden[k] = hv;
    }
}

// ---------------- Kernel A: blocks [0,NATTN) fused attention (independent);
// blocks [NATTN,GRID_A): h1-half of W_out rows (1 row/warp) -> g_part.
__global__ void __launch_bounds__(256) kA(const float* __restrict__ Wa,
                                          const float* __restrict__ enc,
                                          const float* __restrict__ Wout,
                                          float* __restrict__ out_attn) {
    const int t = threadIdx.x;
    const int w = t >> 5, lane = t & 31;

    if (blockIdx.x < NATTN) {
        // ===== attention =====
        const int b = blockIdx.x;
        __shared__ float h1s[8];
        __shared__ float sc[16];
        __shared__ float attnw[16];
        __shared__ float red[8];
        __shared__ float sM, sInvS;

        if (t < 8) h1s[t] = g_h1[b * 8 + t];
        __syncthreads();
        {
            const float4* Wa4 = (const float4*)(Wa + (size_t)(b * 8) * H);
            float4 a = make_float4(0.f, 0.f, 0.f, 0.f);
            #pragma unroll
            for (int j = 0; j < 8; j++) {
                float4 wv = Wa4[j * 256 + t];
                float hv = h1s[j];
                a.x += wv.x * hv; a.y += wv.y * hv; a.z += wv.z * hv; a.w += wv.w * hv;
            }
            atomicAdd(&g_v[4*t + 0], a.x);
            atomicAdd(&g_v[4*t + 1], a.y);
            atomicAdd(&g_v[4*t + 2], a.z);
            atomicAdd(&g_v[4*t + 3], a.w);
        }
        attn_barrier(NATTN);

        const int s0 = b * 16;
        {
            const float4* v4 = (const float4*)g_v;
            float4 vv[8];
            #pragma unroll
            for (int i = 0; i < 8; i++) vv[i] = v4[lane + 32*i];
            const float4* e4a = (const float4*)(enc + (size_t)(s0 + 2*w)     * H);
            const float4* e4b = (const float4*)(enc + (size_t)(s0 + 2*w + 1) * H);
            float acc0 = 0.f, acc1 = 0.f;
            #pragma unroll
            for (int i = 0; i < 8; i++) {
                acc0 += dot4(e4a[lane + 32*i], vv[i]);
                acc1 += dot4(e4b[lane + 32*i], vv[i]);
            }
            acc0 = warp_sum(acc0);
            acc1 = warp_sum(acc1);
            if (lane == 0) { sc[2*w] = acc0; sc[2*w + 1] = acc1; }
        }
        __syncthreads();
        if (t == 0) {
            float m = -INFINITY;
            #pragma unroll
            for (int j = 0; j < 16; j++) m = fmaxf(m, sc[j]);
            float s = 0.f;
            #pragma unroll
            for (int j = 0; j < 16; j++) s += expf(sc[j] - m);
            g_apm[b] = m;
            g_aps[b] = s;
        }
        attn_barrier(2 * NATTN);

        {
            float m = (t < NATTN) ? g_apm[t] : -INFINITY;
            m = warp_max(m);
            if (lane == 0) red[w] = m;
            __syncthreads();
            if (t == 0) {
                float M = -INFINITY;
                #pragma unroll
                for (int j = 0; j < 8; j++) M = fmaxf(M, red[j]);
                sM = M;
            }
            __syncthreads();
            float e = (t < NATTN) ? g_aps[t] * expf(g_apm[t] - sM) : 0.f;
            e = warp_sum(e);
            if (lane == 0) red[w] = e;
            __syncthreads();
            if (t == 0) {
                float Ssum = 0.f;
                #pragma unroll
                for (int j = 0; j < 8; j++) Ssum += red[j];
                sInvS = 1.f / Ssum;
            }
            __syncthreads();
            if (t < 16) {
                float a = expf(sc[t] - sM) * sInvS;
                attnw[t] = a;
                out_attn[s0 + t] = a;
            }
            __syncthreads();
        }
        {
            const float4* e4 = (const float4*)(enc + (size_t)s0 * H);
            float4 c = make_float4(0.f, 0.f, 0.f, 0.f);
            #pragma unroll
            for (int r = 0; r < 16; r++) {
                float av = attnw[r];
                float4 e = e4[r * 256 + t];
                c.x += av * e.x; c.y += av * e.y; c.z += av * e.z; c.w += av * e.w;
            }
            atomicAdd(&g_context[4*t + 0], c.x);
            atomicAdd(&g_context[4*t + 1], c.y);
            atomicAdd(&g_context[4*t + 2], c.z);
            atomicAdd(&g_context[4*t + 3], c.w);
        }
    } else {
        // ===== h1-half logits partial (cols [0,H)), 1 row/warp =====
        const int bb = blockIdx.x - NATTN;
        __shared__ __align__(16) float qs[H];
        for (int i = t; i < H; i += 256) qs[i] = g_h1[i];
        __syncthreads();
        const int r = bb * 8 + w;
        if (r < V) {
            const float4* wr = (const float4*)(Wout + (size_t)r * (2*H));
            const float4* q4 = (const float4*)qs;
            float acc0 = 0.f, acc1 = 0.f;
            #pragma unroll
            for (int i = 0; i < 8; i += 2) {
                acc0 += dot4(wr[lane + i*32],     q4[lane + i*32]);
                acc1 += dot4(wr[lane + (i+1)*32], q4[lane + (i+1)*32]);
            }
            float acc = warp_sum(acc0 + acc1);
            if (lane == 0) g_part[r] = acc;
        }
    }
}

// ---------------- Kernel B: ctx-half (cols [H,2H)), 1 row/warp; combine ->
// logits; one atomicAdd of block sum-exp (shift 0 — logits are O(1)).
__global__ void __launch_bounds__(256) kB(const float* __restrict__ Wout,
                                          const float* __restrict__ bout) {
    const int t = threadIdx.x;
    const int w = t >> 5, lane = t & 31;
    __shared__ __align__(16) float qs[H];
    __shared__ float bexp[8];
    for (int i = t; i < H; i += 256) qs[i] = g_context[i];
    __syncthreads();

    const int r = blockIdx.x * 8 + w;
    float e = 0.f;
    if (r < V) {
        const float4* wr = (const float4*)(Wout + (size_t)r * (2*H) + H);
        const float4* q4 = (const float4*)qs;
        float acc0 = 0.f, acc1 = 0.f;
        #pragma unroll
        for (int i = 0; i < 8; i += 2) {
            acc0 += dot4(wr[lane + i*32],     q4[lane + i*32]);
            acc1 += dot4(wr[lane + (i+1)*32], q4[lane + (i+1)*32]);
        }
        float acc = warp_sum(acc0 + acc1);
        if (lane == 0) {
            float logit = acc + g_part[r] + bout[r];
            g_logits[r] = logit;
            e = expf(logit);
        }
    }
    if (lane == 0) bexp[w] = e;
    __syncthreads();
    if (t == 0) {
        float s = 0.f;
        #pragma unroll
        for (int j = 0; j < 8; j++) s += bexp[j];
        atomicAdd(&g_sumexpv, s);
    }
}

// ---------------- K9: elementwise normalize; block 0 emits context.
__global__ void __launch_bounds__(256) k9_final(float* __restrict__ out,
                                                float* __restrict__ out_ctx) {
    const int t = threadIdx.x;
    if (blockIdx.x == 0) {
        for (int i = t; i < H; i += 256) out_ctx[i] = g_context[i];
    }
    float shift = logf(g_sumexpv);
    int v = blockIdx.x * 256 + t;
    if (v < V) out[v] = g_logits[v] - shift;
}

extern "C" void kernel_launch(void* const* d_in, const int* in_sizes, int n_in,
                              void* d_out, int out_size) {
    const int*   word     = (const int*)  d_in[0];
    const float* last_ctx = (const float*)d_in[1];
    const float* last_hid = (const float*)d_in[2];
    const float* enc      = (const float*)d_in[3];
    const float* emb      = (const float*)d_in[4];
    const float* W_ih0    = (const float*)d_in[5];
    const float* W_hh0    = (const float*)d_in[6];
    const float* b_ih0    = (const float*)d_in[7];
    const float* b_hh0    = (const float*)d_in[8];
    const float* W_ih1    = (const float*)d_in[9];
    const float* W_hh1    = (const float*)d_in[10];
    const float* b_ih1    = (const float*)d_in[11];
    const float* b_hh1    = (const float*)d_in[12];
    const float* Wa       = (const float*)d_in[13];
    // d_in[14] = ba (cancels under softmax shift-invariance)
    const float* W_out    = (const float*)d_in[15];
    const float* b_out    = (const float*)d_in[16];
    float* out = (float*)d_out;

    float *g_h0_p, *g_h1_p;
    cudaGetSymbolAddress((void**)&g_h0_p, g_h0);
    cudaGetSymbolAddress((void**)&g_h1_p, g_h1);

    k_gru<true ><<<H, 256>>>(word, emb, last_ctx, nullptr, last_hid,
                             W_ih0, W_hh0, b_ih0, b_hh0,
                             g_h0_p, out + OUT_HID, 0);
    k_gru<false><<<H, 256>>>(nullptr, nullptr, nullptr, g_h0_p, last_hid + H,
                             W_ih1, W_hh1, b_ih1, b_hh1,
                             g_h1_p, out + OUT_HID + H, 1);
    kA<<<GRID_A, 256>>>(Wa, enc, W_out, out + OUT_ATTN);
    kB<<<NBK, 256>>>(W_out, b_out);
    k9_final<<<(V + 255) / 256, 256>>>(out, out + OUT_CTX);
}

// round 9
// speedup vs baseline: 1.2090x; 1.0375x over previous
#include <cuda_runtime.h>
#include <math.h>

#define V 50257
#define H 1024
#define S 2048
#define NATTN 128               // attention blocks (wave-1 resident by ID)
#define NBK 6283                // ceil(V/8), 8 rows per logits block
#define GRID_A (NATTN + NBK)

// out layout: [0,V) log_softmax | [V,V+H) context | [V+H,V+3H) hidden | [V+3H,V+3H+S) attn
#define OUT_CTX  (V)
#define OUT_HID  (V + H)
#define OUT_ATTN (V + 3*H)

// float4-accessed globals MUST be 16B aligned (round-4 trap)
__device__ __align__(16) float g_h0[H];
__device__ __align__(16) float g_h1[H];
__device__ __align__(16) float g_v[H];
__device__ __align__(16) float g_context[H];
__device__ __align__(16) float g_logits[V];
__device__ __align__(16) float g_part[NBK * 8];   // h1-half partial per row
__device__ __align__(16) float g_gh1[3 * H];      // GRU1 hidden-gate partials
__device__ float g_apm[NATTN];
__device__ float g_aps[NATTN];
__device__ float g_sumexpv;        // global sum of exp(logit), shift 0 (logits are O(1))
__device__ unsigned g_barrier;     // attention-internal barrier

__device__ __forceinline__ float warp_sum(float v) {
    #pragma unroll
    for (int o = 16; o; o >>= 1) v += __shfl_down_sync(0xffffffffu, v, o);
    return v;
}
__device__ __forceinline__ float warp_max(float v) {
    #pragma unroll
    for (int o = 16; o; o >>= 1) v = fmaxf(v, __shfl_down_sync(0xffffffffu, v, o));
    return v;
}
__device__ __forceinline__ float dot4(float4 a, float4 b) {
    return a.x*b.x + a.y*b.y + a.z*b.z + a.w*b.w;
}
// barrier among the NATTN attention blocks only (IDs 0..127 -> wave-1 resident)
__device__ __forceinline__ void attn_barrier(unsigned target) {
    __syncthreads();
    if (threadIdx.x == 0) {
        __threadfence();
        atomicAdd(&g_barrier, 1u);
        volatile unsigned* p = &g_barrier;
        while (*p < target) __nanosleep(32);
        __threadfence();
    }
    __syncthreads();
}

// ---------------- G1: blocks [0,H): GRU0 row k (x = [emb[word], last_ctx]).
// blocks [H,2H): GRU1 hidden-gate partials gh1 = W_hh1 · last_hid1 (indep of h0).
__global__ void __launch_bounds__(256) kG1(const int* __restrict__ word,
                                           const float* __restrict__ emb,
                                           const float* __restrict__ last_ctx,
                                           const float* __restrict__ last_hid,
                                           const float* __restrict__ W_ih0,
                                           const float* __restrict__ W_hh0,
                                           const float* __restrict__ b_ih0,
                                           const float* __restrict__ b_hh0,
                                           const float* __restrict__ W_hh1,
                                           float* __restrict__ out_hidden0) {
    const int t = threadIdx.x;                 // 256
    const int w = t >> 5, lane = t & 31;
    __shared__ float red[6][8];

    if (blockIdx.x < H) {
        // ===== GRU0 row k =====
        const int k = blockIdx.x;
        if (t == 0) {
            g_v[k] = 0.f;
            g_context[k] = 0.f;
            if (k == 0) { g_barrier = 0u; g_sumexpv = 0.f; }
        }
        int wi = word[0];
        const float4* xa4 = (const float4*)(emb + (size_t)wi * H);
        const float4* xb4 = (const float4*)last_ctx;
        const float4* h4  = (const float4*)last_hid;      // hidden layer 0
        float acc[6];
        #pragma unroll
        for (int g = 0; g < 3; g++) {
            const float* wrow = W_ih0 + (size_t)(g * H + k) * (2*H);
            float a  = dot4(((const float4*)wrow)[t],       xa4[t]);
            a       += dot4(((const float4*)(wrow + H))[t], xb4[t]);
            acc[g] = a;
        }
        #pragma unroll
        for (int g = 0; g < 3; g++) {
            const float* wrow = W_hh0 + (size_t)(g * H + k) * H;
            acc[3 + g] = dot4(((const float4*)wrow)[t], h4[t]);
        }
        #pragma unroll
        for (int g = 0; g < 6; g++) {
            float s = warp_sum(acc[g]);
            if (lane == 0) red[g][w] = s;
        }
        __syncthreads();
        if (t == 0) {
            float s[6];
            #pragma unroll
            for (int g = 0; g < 6; g++) {
                float a = 0.f;
                #pragma unroll
                for (int j = 0; j < 8; j++) a += red[g][j];
                s[g] = a;
            }
            float ir = s[0] + b_ih0[k],       hr = s[3] + b_hh0[k];
            float iz = s[1] + b_ih0[H + k],   hz = s[4] + b_hh0[H + k];
            float in_= s[2] + b_ih0[2*H + k], hn = s[5] + b_hh0[2*H + k];
            float r = 1.f / (1.f + expf(-(ir + hr)));
            float z = 1.f / (1.f + expf(-(iz + hz)));
            float n = tanhf(in_ + r * hn);
            float hv = (1.f - z) * n + z * last_hid[k];
            g_h0[k] = hv;
            out_hidden0[k] = hv;
        }
    } else {
        // ===== GRU1 gh partials for row k =====
        const int k = blockIdx.x - H;
        const float4* h4 = (const float4*)(last_hid + H); // hidden layer 1
        float acc[3];
        #pragma unroll
        for (int g = 0; g < 3; g++) {
            const float* wrow = W_hh1 + (size_t)(g * H + k) * H;
            acc[g] = dot4(((const float4*)wrow)[t], h4[t]);
        }
        #pragma unroll
        for (int g = 0; g < 3; g++) {
            float s = warp_sum(acc[g]);
            if (lane == 0) red[g][w] = s;
        }
        __syncthreads();
        if (t == 0) {
            #pragma unroll
            for (int g = 0; g < 3; g++) {
                float a = 0.f;
                #pragma unroll
                for (int j = 0; j < 8; j++) a += red[g][j];
                g_gh1[g * H + k] = a;
            }
        }
    }
}

// ---------------- G2: GRU1 input gates gi = W_ih1 · h0; combine with g_gh1.
__global__ void __launch_bounds__(256) kG2(const float* __restrict__ W_ih1,
                                           const float* __restrict__ b_ih1,
                                           const float* __restrict__ b_hh1,
                                           const float* __restrict__ last_hid,
                                           float* __restrict__ out_hidden1) {
    const int k = blockIdx.x;
    const int t = threadIdx.x;
    const int w = t >> 5, lane = t & 31;
    __shared__ float red[3][8];
    const float4* x4 = (const float4*)g_h0;
    float acc[3];
    #pragma unroll
    for (int g = 0; g < 3; g++) {
        const float* wrow = W_ih1 + (size_t)(g * H + k) * H;
        acc[g] = dot4(((const float4*)wrow)[t], x4[t]);
    }
    #pragma unroll
    for (int g = 0; g < 3; g++) {
        float s = warp_sum(acc[g]);
        if (lane == 0) red[g][w] = s;
    }
    __syncthreads();
    if (t == 0) {
        float s[3];
        #pragma unroll
        for (int g = 0; g < 3; g++) {
            float a = 0.f;
            #pragma unroll
            for (int j = 0; j < 8; j++) a += red[g][j];
            s[g] = a;
        }
        float hprev = last_hid[H + k];
        float ir = s[0] + b_ih1[k],       hr = g_gh1[k]       + b_hh1[k];
        float iz = s[1] + b_ih1[H + k],   hz = g_gh1[H + k]   + b_hh1[H + k];
        float in_= s[2] + b_ih1[2*H + k], hn = g_gh1[2*H + k] + b_hh1[2*H + k];
        float r = 1.f / (1.f + expf(-(ir + hr)));
        float z = 1.f / (1.f + expf(-(iz + hz)));
        float n = tanhf(in_ + r * hn);
        float hv = (1.f - z) * n + z * hprev;
        g_h1[k] = hv;
        out_hidden1[k] = hv;
    }
}

// ---------------- Kernel A: blocks [0,NATTN) fused attention (independent);
// blocks [NATTN,GRID_A): h1-half of W_out rows (1 row/warp) -> g_part.
__global__ void __launch_bounds__(256, 6) kA(const float* __restrict__ Wa,
                                             const float* __restrict__ enc,
                                             const float* __restrict__ Wout,
                                             float* __restrict__ out_attn) {
    const int t = threadIdx.x;
    const int w = t >> 5, lane = t & 31;

    if (blockIdx.x < NATTN) {
        // ===== attention =====
        const int b = blockIdx.x;
        __shared__ float h1s[8];
        __shared__ float sc[16];
        __shared__ float attnw[16];
        __shared__ float red[8];
        __shared__ float sM, sInvS;

        if (t < 8) h1s[t] = g_h1[b * 8 + t];
        __syncthreads();
        {
            const float4* Wa4 = (const float4*)(Wa + (size_t)(b * 8) * H);
            float4 a = make_float4(0.f, 0.f, 0.f, 0.f);
            #pragma unroll
            for (int j = 0; j < 8; j++) {
                float4 wv = Wa4[j * 256 + t];
                float hv = h1s[j];
                a.x += wv.x * hv; a.y += wv.y * hv; a.z += wv.z * hv; a.w += wv.w * hv;
            }
            atomicAdd(&g_v[4*t + 0], a.x);
            atomicAdd(&g_v[4*t + 1], a.y);
            atomicAdd(&g_v[4*t + 2], a.z);
            atomicAdd(&g_v[4*t + 3], a.w);
        }
        attn_barrier(NATTN);

        const int s0 = b * 16;
        {
            const float4* v4 = (const float4*)g_v;
            float4 vv[8];
            #pragma unroll
            for (int i = 0; i < 8; i++) vv[i] = v4[lane + 32*i];
            const float4* e4a = (const float4*)(enc + (size_t)(s0 + 2*w)     * H);
            const float4* e4b = (const float4*)(enc + (size_t)(s0 + 2*w + 1) * H);
            float acc0 = 0.f, acc1 = 0.f;
            #pragma unroll
            for (int i = 0; i < 8; i++) {
                acc0 += dot4(e4a[lane + 32*i], vv[i]);
                acc1 += dot4(e4b[lane + 32*i], vv[i]);
            }
            acc0 = warp_sum(acc0);
            acc1 = warp_sum(acc1);
            if (lane == 0) { sc[2*w] = acc0; sc[2*w + 1] = acc1; }
        }
        __syncthreads();
        if (t == 0) {
            float m = -INFINITY;
            #pragma unroll
            for (int j = 0; j < 16; j++) m = fmaxf(m, sc[j]);
            float s = 0.f;
            #pragma unroll
            for (int j = 0; j < 16; j++) s += expf(sc[j] - m);
            g_apm[b] = m;
            g_aps[b] = s;
        }
        attn_barrier(2 * NATTN);

        {
            float m = (t < NATTN) ? g_apm[t] : -INFINITY;
            m = warp_max(m);
            if (lane == 0) red[w] = m;
            __syncthreads();
            if (t == 0) {
                float M = -INFINITY;
                #pragma unroll
                for (int j = 0; j < 8; j++) M = fmaxf(M, red[j]);
                sM = M;
            }
            __syncthreads();
            float e = (t < NATTN) ? g_aps[t] * expf(g_apm[t] - sM) : 0.f;
            e = warp_sum(e);
            if (lane == 0) red[w] = e;
            __syncthreads();
            if (t == 0) {
                float Ssum = 0.f;
                #pragma unroll
                for (int j = 0; j < 8; j++) Ssum += red[j];
                sInvS = 1.f / Ssum;
            }
            __syncthreads();
            if (t < 16) {
                float a = expf(sc[t] - sM) * sInvS;
                attnw[t] = a;
                out_attn[s0 + t] = a;
            }
            __syncthreads();
        }
        {
            const float4* e4 = (const float4*)(enc + (size_t)s0 * H);
            float4 c = make_float4(0.f, 0.f, 0.f, 0.f);
            #pragma unroll
            for (int r = 0; r < 16; r++) {
                float av = attnw[r];
                float4 e = e4[r * 256 + t];
                c.x += av * e.x; c.y += av * e.y; c.z += av * e.z; c.w += av * e.w;
            }
            atomicAdd(&g_context[4*t + 0], c.x);
            atomicAdd(&g_context[4*t + 1], c.y);
            atomicAdd(&g_context[4*t + 2], c.z);
            atomicAdd(&g_context[4*t + 3], c.w);
        }
    } else {
        // ===== h1-half logits partial (cols [0,H)), 1 row/warp =====
        const int bb = blockIdx.x - NATTN;
        __shared__ __align__(16) float qs[H];
        for (int i = t; i < H; i += 256) qs[i] = g_h1[i];
        __syncthreads();
        const int r = bb * 8 + w;
        if (r < V) {
            const float4* wr = (const float4*)(Wout + (size_t)r * (2*H));
            const float4* q4 = (const float4*)qs;
            float acc0 = 0.f, acc1 = 0.f;
            #pragma unroll
            for (int i = 0; i < 8; i += 2) {
                acc0 += dot4(__ldcs(&wr[lane + i*32]),     q4[lane + i*32]);
                acc1 += dot4(__ldcs(&wr[lane + (i+1)*32]), q4[lane + (i+1)*32]);
            }
            float acc = warp_sum(acc0 + acc1);
            if (lane == 0) g_part[r] = acc;
        }
    }
}

// ---------------- Kernel B: ctx-half (cols [H,2H)), 1 row/warp; combine ->
// logits; one atomicAdd of block sum-exp (shift 0 — logits are O(1)).
__global__ void __launch_bounds__(256, 6) kB(const float* __restrict__ Wout,
                                             const float* __restrict__ bout) {
    const int t = threadIdx.x;
    const int w = t >> 5, lane = t & 31;
    __shared__ __align__(16) float qs[H];
    __shared__ float bexp[8];
    for (int i = t; i < H; i += 256) qs[i] = g_context[i];
    __syncthreads();

    const int r = blockIdx.x * 8 + w;
    float e = 0.f;
    if (r < V) {
        const float4* wr = (const float4*)(Wout + (size_t)r * (2*H) + H);
        const float4* q4 = (const float4*)qs;
        float acc0 = 0.f, acc1 = 0.f;
        #pragma unroll
        for (int i = 0; i < 8; i += 2) {
            acc0 += dot4(__ldcs(&wr[lane + i*32]),     q4[lane + i*32]);
            acc1 += dot4(__ldcs(&wr[lane + (i+1)*32]), q4[lane + (i+1)*32]);
        }
        float acc = warp_sum(acc0 + acc1);
        if (lane == 0) {
            float logit = acc + g_part[r] + bout[r];
            g_logits[r] = logit;
            e = expf(logit);
        }
    }
    if (lane == 0) bexp[w] = e;
    __syncthreads();
    if (t == 0) {
        float s = 0.f;
        #pragma unroll
        for (int j = 0; j < 8; j++) s += bexp[j];
        atomicAdd(&g_sumexpv, s);
    }
}

// ---------------- K9: elementwise normalize; block 0 emits context.
__global__ void __launch_bounds__(256) k9_final(float* __restrict__ out,
                                                float* __restrict__ out_ctx) {
    const int t = threadIdx.x;
    if (blockIdx.x == 0) {
        for (int i = t; i < H; i += 256) out_ctx[i] = g_context[i];
    }
    float shift = logf(g_sumexpv);
    int v = blockIdx.x * 256 + t;
    if (v < V) out[v] = g_logits[v] - shift;
}

extern "C" void kernel_launch(void* const* d_in, const int* in_sizes, int n_in,
                              void* d_out, int out_size) {
    const int*   word     = (const int*)  d_in[0];
    const float* last_ctx = (const float*)d_in[1];
    const float* last_hid = (const float*)d_in[2];
    const float* enc      = (const float*)d_in[3];
    const float* emb      = (const float*)d_in[4];
    const float* W_ih0    = (const float*)d_in[5];
    const float* W_hh0    = (const float*)d_in[6];
    const float* b_ih0    = (const float*)d_in[7];
    const float* b_hh0    = (const float*)d_in[8];
    const float* W_ih1    = (const float*)d_in[9];
    const float* W_hh1    = (const float*)d_in[10];
    const float* b_ih1    = (const float*)d_in[11];
    const float* b_hh1    = (const float*)d_in[12];
    const float* Wa       = (const float*)d_in[13];
    // d_in[14] = ba (cancels under softmax shift-invariance)
    const float* W_out    = (const float*)d_in[15];
    const float* b_out    = (const float*)d_in[16];
    float* out = (float*)d_out;

    kG1<<<2*H, 256>>>(word, emb, last_ctx, last_hid,
                      W_ih0, W_hh0, b_ih0, b_hh0, W_hh1,
                      out + OUT_HID);
    kG2<<<H, 256>>>(W_ih1, b_ih1, b_hh1, last_hid, out + OUT_HID + H);
    kA<<<GRID_A, 256>>>(Wa, enc, W_out, out + OUT_ATTN);
    kB<<<NBK, 256>>>(W_out, b_out);
    k9_final<<<(V + 255) / 256, 256>>>(out, out + OUT_CTX);
}